// round 2
// baseline (speedup 1.0000x reference)
#include <cuda_runtime.h>
#include <math.h>

// Problem constants (fixed shapes from reference)
#define DIMX   2048
#define HEADS  16
#define HD     128            // DIM / HEADS
#define BATCH  4
#define SEQ    2048
#define M_TOT  (BATCH * SEQ)  // 8192 rows of x
#define N_TOT  (4 * DIMX)     // 8192 projection outputs
#define K_TOT  DIMX           // 2048

// Scan chunking
#define NCHUNK 32
#define CLEN   (SEQ / NCHUNK) // 64
#define NCH    (BATCH * HEADS * HD) // 8192 independent cummax channels

// Scratch: combined projection [M_TOT, N_TOT] fp32 (256 MB), chunk maxima (1 MB)
__device__ float g_combined[(size_t)M_TOT * N_TOT];
__device__ float g_chunkmax[(size_t)NCHUNK * NCH];

// ---------------------------------------------------------------------------
// Kernel 1: C[M,N] = A[M,K] * B[N,K]^T   (x @ W^T), fp32 SIMT SGEMM
// 128x128 block tile, BK=16, 256 threads, 8x8 per thread
// ---------------------------------------------------------------------------
#define BM 128
#define BN 128
#define BK 16
#define TM 8
#define TN 8

__global__ __launch_bounds__(256, 2)
void sgemm_kernel(const float* __restrict__ A, const float* __restrict__ B) {
    __shared__ float As[BK][BM];
    __shared__ float Bs[BK][BN];

    const int tid = threadIdx.x;
    const int bm  = blockIdx.y * BM;
    const int bn  = blockIdx.x * BN;

    // Tile load mapping: 128 rows x 16 cols as float4; 256 threads x 2 rows
    const int lrow = tid >> 2;          // 0..63
    const int lcol = (tid & 3) * 4;     // 0,4,8,12

    const int ty = (tid >> 4) * TM;     // 0..120
    const int tx = (tid & 15) * TN;     // 0..120

    float acc[TM][TN];
    #pragma unroll
    for (int i = 0; i < TM; i++)
        #pragma unroll
        for (int j = 0; j < TN; j++) acc[i][j] = 0.0f;

    const float* Aptr = A + (size_t)bm * K_TOT;
    const float* Bptr = B + (size_t)bn * K_TOT;

    for (int k0 = 0; k0 < K_TOT; k0 += BK) {
        #pragma unroll
        for (int r = 0; r < 2; r++) {
            const int row = lrow + r * 64;
            float4 va = *(const float4*)(Aptr + (size_t)row * K_TOT + k0 + lcol);
            As[lcol + 0][row] = va.x;
            As[lcol + 1][row] = va.y;
            As[lcol + 2][row] = va.z;
            As[lcol + 3][row] = va.w;
            float4 vb = *(const float4*)(Bptr + (size_t)row * K_TOT + k0 + lcol);
            Bs[lcol + 0][row] = vb.x;
            Bs[lcol + 1][row] = vb.y;
            Bs[lcol + 2][row] = vb.z;
            Bs[lcol + 3][row] = vb.w;
        }
        __syncthreads();

        #pragma unroll
        for (int k = 0; k < BK; k++) {
            float ra[TM], rb[TN];
            #pragma unroll
            for (int i = 0; i < TM; i++) ra[i] = As[k][ty + i];
            #pragma unroll
            for (int j = 0; j < TN; j++) rb[j] = Bs[k][tx + j];
            #pragma unroll
            for (int i = 0; i < TM; i++)
                #pragma unroll
                for (int j = 0; j < TN; j++)
                    acc[i][j] = fmaf(ra[i], rb[j], acc[i][j]);
        }
        __syncthreads();
    }

    #pragma unroll
    for (int i = 0; i < TM; i++) {
        float* Crow = g_combined + (size_t)(bm + ty + i) * N_TOT + bn + tx;
        *(float4*)(Crow + 0) = make_float4(acc[i][0], acc[i][1], acc[i][2], acc[i][3]);
        *(float4*)(Crow + 4) = make_float4(acc[i][4], acc[i][5], acc[i][6], acc[i][7]);
    }
}

// ---------------------------------------------------------------------------
// Kernel 2: per-(channel, chunk) max of c over its sequence chunk
// channel ch = b*HEADS*HD + head*HD + hd; c = combined[:, 2*DIM + head*HD + hd]
// ---------------------------------------------------------------------------
__global__ void chunkmax_kernel() {
    const int idx = blockIdx.x * blockDim.x + threadIdx.x;
    if (idx >= NCH * NCHUNK) return;
    const int ch    = idx % NCH;      // consecutive threads -> consecutive hd (coalesced)
    const int chunk = idx / NCH;

    const int b    = ch / (HEADS * HD);
    const int rem  = ch % (HEADS * HD);
    const int head = rem / HD;
    const int hd   = rem % HD;

    const float* cptr = g_combined + (size_t)b * SEQ * N_TOT
                        + (size_t)2 * DIMX + (size_t)head * HD + hd;
    float m = -INFINITY;
    const int s0 = chunk * CLEN;
    for (int s = s0; s < s0 + CLEN; s++) {
        m = fmaxf(m, cptr[(size_t)s * N_TOT]);
    }
    g_chunkmax[(size_t)chunk * NCH + ch] = m;
}

// ---------------------------------------------------------------------------
// Kernel 3: carry-in from previous chunk maxima, running cummax, fused
// elementwise combine, transposed store; writes state from final chunk.
// out = bb*(a + a1 + c + e) + a2*dd + a*(a3*e + dd) + c*e
// ---------------------------------------------------------------------------
__global__ void scan_out_kernel(const float* __restrict__ alphas,
                                float* __restrict__ out,
                                long long out_size) {
    const int idx = blockIdx.x * blockDim.x + threadIdx.x;
    if (idx >= NCH * NCHUNK) return;
    const int ch    = idx % NCH;
    const int chunk = idx / NCH;

    const int b    = ch / (HEADS * HD);
    const int rem  = ch % (HEADS * HD);
    const int head = rem / HD;
    const int hd   = rem % HD;

    const float a1 = alphas[0];
    const float a2 = alphas[1];
    const float a3 = alphas[2];

    // exclusive prefix max over earlier chunks (carry-in)
    float e = -INFINITY;
    for (int j = 0; j < chunk; j++)
        e = fmaxf(e, g_chunkmax[(size_t)j * NCH + ch]);

    const float* base = g_combined + (size_t)b * SEQ * N_TOT + (size_t)head * HD + hd;
    float* outp = out + (size_t)b * SEQ * DIMX + (size_t)hd * HEADS + head;

    const int s0 = chunk * CLEN;
    for (int s = s0; s < s0 + CLEN; s++) {
        const float* row = base + (size_t)s * N_TOT;
        const float av = row[0];
        const float bv = row[DIMX];
        const float cv = row[2 * DIMX];
        const float dv = row[3 * DIMX];
        e = fmaxf(e, cv);
        const float o = bv * (av + a1 + cv + e) + a2 * dv
                        + av * fmaf(a3, e, dv) + cv * e;
        outp[(size_t)s * DIMX] = o;
    }

    // state[b, hd, 0, head] = final cummax value, appended after `out`
    if (chunk == NCHUNK - 1) {
        const size_t state_base = (size_t)BATCH * SEQ * DIMX;
        if (out_size >= (long long)(state_base + (size_t)BATCH * HD * HEADS)) {
            out[state_base + (size_t)b * HD * HEADS + (size_t)hd * HEADS + head] = e;
        }
    }
}

// ---------------------------------------------------------------------------
extern "C" void kernel_launch(void* const* d_in, const int* in_sizes, int n_in,
                              void* d_out, int out_size) {
    const float* x      = (const float*)d_in[0]; // [4, 2048, 2048]
    const float* W      = (const float*)d_in[1]; // [8192, 2048]
    const float* alphas = (const float*)d_in[2]; // [4]
    float* out = (float*)d_out;

    dim3 gemm_grid(N_TOT / BN, M_TOT / BM);      // (64, 64)
    sgemm_kernel<<<gemm_grid, 256>>>(x, W);

    const int scan_threads = NCH * NCHUNK;       // 262144
    chunkmax_kernel<<<(scan_threads + 255) / 256, 256>>>();
    scan_out_kernel<<<(scan_threads + 255) / 256, 256>>>(alphas, out, (long long)out_size);
}

// round 3
// speedup vs baseline: 3.1486x; 3.1486x over previous
#include <cuda_runtime.h>
#include <math.h>
#include <stdint.h>

// Problem constants (fixed shapes from reference)
#define DIMX   2048
#define HEADS  16
#define HD     128            // DIM / HEADS
#define BATCH  4
#define SEQ    2048
#define M_TOT  (BATCH * SEQ)  // 8192
#define N_TOT  (4 * DIMX)     // 8192
#define K_TOT  DIMX           // 2048

// Scan chunking
#define NCHUNK 32
#define CLEN   (SEQ / NCHUNK) // 64
#define NCH    (BATCH * HEADS * HD) // 8192

// Scratch
__device__ float g_combined[(size_t)M_TOT * N_TOT];          // 256 MB
__device__ float g_chunkmax[(size_t)NCHUNK * NCH];           // 1 MB
__device__ float g_Ar[(size_t)M_TOT * K_TOT];                // 64 MB (tf32-rounded x)
__device__ float g_Br[(size_t)N_TOT * K_TOT];                // 64 MB (tf32-rounded W)

// ---------------------------------------------------------------------------
// PTX helpers
// ---------------------------------------------------------------------------
__device__ __forceinline__ uint32_t f2tf32(float f) {
    uint32_t o;
    asm("cvt.rna.tf32.f32 %0, %1;" : "=r"(o) : "f"(f));
    return o;
}
__device__ __forceinline__ void cp_async16(uint32_t dst_smem, const void* src) {
    asm volatile("cp.async.cg.shared.global [%0], [%1], 16;\n" :: "r"(dst_smem), "l"(src));
}
__device__ __forceinline__ void cp_commit() {
    asm volatile("cp.async.commit_group;\n");
}
template <int N>
__device__ __forceinline__ void cp_wait() {
    asm volatile("cp.async.wait_group %0;\n" :: "n"(N));
}
__device__ __forceinline__ void mma_tf32(float& c0, float& c1, float& c2, float& c3,
                                         uint32_t a0, uint32_t a1, uint32_t a2, uint32_t a3,
                                         uint32_t b0, uint32_t b1) {
    asm volatile(
        "mma.sync.aligned.m16n8k8.row.col.f32.tf32.tf32.f32 "
        "{%0,%1,%2,%3}, {%4,%5,%6,%7}, {%8,%9}, {%0,%1,%2,%3};\n"
        : "+f"(c0), "+f"(c1), "+f"(c2), "+f"(c3)
        : "r"(a0), "r"(a1), "r"(a2), "r"(a3), "r"(b0), "r"(b1));
}

// ---------------------------------------------------------------------------
// Kernel 0: round x and W to tf32 (rna) into scratch copies
// ---------------------------------------------------------------------------
__global__ void cvt_kernel(const float4* __restrict__ x, const float4* __restrict__ w) {
    const size_t N4 = (size_t)M_TOT * K_TOT / 4;   // per-tensor float4 count
    size_t i = (size_t)blockIdx.x * blockDim.x + threadIdx.x;
    float4* Ao = (float4*)g_Ar;
    float4* Bo = (float4*)g_Br;
    if (i < N4) {
        float4 v = x[i];
        float4 o;
        o.x = __uint_as_float(f2tf32(v.x));
        o.y = __uint_as_float(f2tf32(v.y));
        o.z = __uint_as_float(f2tf32(v.z));
        o.w = __uint_as_float(f2tf32(v.w));
        Ao[i] = o;
    } else if (i < 2 * N4) {
        size_t j = i - N4;
        float4 v = w[j];
        float4 o;
        o.x = __uint_as_float(f2tf32(v.x));
        o.y = __uint_as_float(f2tf32(v.y));
        o.z = __uint_as_float(f2tf32(v.z));
        o.w = __uint_as_float(f2tf32(v.w));
        Bo[j] = o;
    }
}

// ---------------------------------------------------------------------------
// Kernel 1: TF32 tensor-core GEMM  C[M,N] = A[M,K] * B[N,K]^T
// 128x128x16 block tile, 256 threads, 8 warps (2x4), warp tile 64x32
// ---------------------------------------------------------------------------
#define BM 128
#define BN 128
#define BK 16
#define LDT 20                  // BK + 4 pad: conflict-free fragment LDS
#define KT  (K_TOT / BK)        // 128

__global__ __launch_bounds__(256, 2)
void gemm_tf32_kernel() {
    __shared__ float As[2][BM * LDT];
    __shared__ float Bs[2][BN * LDT];

    const int tid  = threadIdx.x;
    const int bm   = blockIdx.y * BM;
    const int bn   = blockIdx.x * BN;

    const int warp = tid >> 5;
    const int lane = tid & 31;
    const int wm   = (warp >> 2) * 64;   // warp tile m origin (0 or 64)
    const int wn   = (warp & 3) * 32;    // warp tile n origin
    const int grp  = lane >> 2;          // 0..7
    const int tig  = lane & 3;           // 0..3

    // tile-load mapping: 512 float4 per tile; thread handles i=tid, i=tid+256
    const int r0 = tid >> 2;            // 0..63
    const int c0 = (tid & 3) * 4;       // 0,4,8,12

    const float* Ag = g_Ar + (size_t)bm * K_TOT;
    const float* Bg = g_Br + (size_t)bn * K_TOT;

    uint32_t sA = (uint32_t)__cvta_generic_to_shared(&As[0][0]);
    uint32_t sB = (uint32_t)__cvta_generic_to_shared(&Bs[0][0]);
    const uint32_t bufBytesA = BM * LDT * 4;
    const uint32_t bufBytesB = BN * LDT * 4;

    float acc[4][4][4];
    #pragma unroll
    for (int i = 0; i < 4; i++)
        #pragma unroll
        for (int j = 0; j < 4; j++)
            #pragma unroll
            for (int v = 0; v < 4; v++) acc[i][j][v] = 0.0f;

    // prefetch tile 0
    {
        const int k0 = 0;
        #pragma unroll
        for (int h = 0; h < 2; h++) {
            const int row = r0 + h * 64;
            cp_async16(sA + (row * LDT + c0) * 4, Ag + (size_t)row * K_TOT + k0 + c0);
            cp_async16(sB + (row * LDT + c0) * 4, Bg + (size_t)row * K_TOT + k0 + c0);
        }
        cp_commit();
    }

    for (int kt = 0; kt < KT; kt++) {
        const int cur = kt & 1;
        if (kt + 1 < KT) {
            const int nxt = (kt + 1) & 1;
            const int k0 = (kt + 1) * BK;
            #pragma unroll
            for (int h = 0; h < 2; h++) {
                const int row = r0 + h * 64;
                cp_async16(sA + nxt * bufBytesA + (row * LDT + c0) * 4,
                           Ag + (size_t)row * K_TOT + k0 + c0);
                cp_async16(sB + nxt * bufBytesB + (row * LDT + c0) * 4,
                           Bg + (size_t)row * K_TOT + k0 + c0);
            }
            cp_commit();
            cp_wait<1>();
        } else {
            cp_wait<0>();
        }
        __syncthreads();

        const uint32_t* Asb = (const uint32_t*)&As[cur][0];
        const uint32_t* Bsb = (const uint32_t*)&Bs[cur][0];

        #pragma unroll
        for (int ks = 0; ks < 2; ks++) {
            const int kc = ks * 8 + tig;
            uint32_t a[4][4];
            #pragma unroll
            for (int mf = 0; mf < 4; mf++) {
                const int rA = wm + mf * 16 + grp;
                a[mf][0] = Asb[rA * LDT + kc];
                a[mf][1] = Asb[(rA + 8) * LDT + kc];
                a[mf][2] = Asb[rA * LDT + kc + 4];
                a[mf][3] = Asb[(rA + 8) * LDT + kc + 4];
            }
            uint32_t b[4][2];
            #pragma unroll
            for (int nf = 0; nf < 4; nf++) {
                const int rB = wn + nf * 8 + grp;
                b[nf][0] = Bsb[rB * LDT + kc];
                b[nf][1] = Bsb[rB * LDT + kc + 4];
            }
            #pragma unroll
            for (int mf = 0; mf < 4; mf++)
                #pragma unroll
                for (int nf = 0; nf < 4; nf++)
                    mma_tf32(acc[mf][nf][0], acc[mf][nf][1], acc[mf][nf][2], acc[mf][nf][3],
                             a[mf][0], a[mf][1], a[mf][2], a[mf][3],
                             b[nf][0], b[nf][1]);
        }
        __syncthreads();
    }

    // write back: c0,c1 at (row, col..col+1), c2,c3 at (row+8, ...)
    #pragma unroll
    for (int mf = 0; mf < 4; mf++) {
        const int row = bm + wm + mf * 16 + grp;
        #pragma unroll
        for (int nf = 0; nf < 4; nf++) {
            const int col = bn + wn + nf * 8 + 2 * tig;
            float2* p0 = (float2*)(g_combined + (size_t)row * N_TOT + col);
            float2* p1 = (float2*)(g_combined + (size_t)(row + 8) * N_TOT + col);
            *p0 = make_float2(acc[mf][nf][0], acc[mf][nf][1]);
            *p1 = make_float2(acc[mf][nf][2], acc[mf][nf][3]);
        }
    }
}

// ---------------------------------------------------------------------------
// Kernel 2: per-(channel, chunk) max of c over its sequence chunk
// ---------------------------------------------------------------------------
__global__ void chunkmax_kernel() {
    const int idx = blockIdx.x * blockDim.x + threadIdx.x;
    if (idx >= NCH * NCHUNK) return;
    const int ch    = idx % NCH;
    const int chunk = idx / NCH;

    const int b    = ch / (HEADS * HD);
    const int rem  = ch % (HEADS * HD);
    const int head = rem / HD;
    const int hd   = rem % HD;

    const float* cptr = g_combined + (size_t)b * SEQ * N_TOT
                        + (size_t)2 * DIMX + (size_t)head * HD + hd;
    float m = -INFINITY;
    const int s0 = chunk * CLEN;
    for (int s = s0; s < s0 + CLEN; s++) {
        m = fmaxf(m, cptr[(size_t)s * N_TOT]);
    }
    g_chunkmax[(size_t)chunk * NCH + ch] = m;
}

// ---------------------------------------------------------------------------
// Kernel 3: carry-in, running cummax, fused combine, transposed store + state
// ---------------------------------------------------------------------------
__global__ void scan_out_kernel(const float* __restrict__ alphas,
                                float* __restrict__ out,
                                long long out_size) {
    const int idx = blockIdx.x * blockDim.x + threadIdx.x;
    if (idx >= NCH * NCHUNK) return;
    const int ch    = idx % NCH;
    const int chunk = idx / NCH;

    const int b    = ch / (HEADS * HD);
    const int rem  = ch % (HEADS * HD);
    const int head = rem / HD;
    const int hd   = rem % HD;

    const float a1 = alphas[0];
    const float a2 = alphas[1];
    const float a3 = alphas[2];

    float e = -INFINITY;
    for (int j = 0; j < chunk; j++)
        e = fmaxf(e, g_chunkmax[(size_t)j * NCH + ch]);

    const float* base = g_combined + (size_t)b * SEQ * N_TOT + (size_t)head * HD + hd;
    float* outp = out + (size_t)b * SEQ * DIMX + (size_t)hd * HEADS + head;

    const int s0 = chunk * CLEN;
    for (int s = s0; s < s0 + CLEN; s++) {
        const float* row = base + (size_t)s * N_TOT;
        const float av = row[0];
        const float bv = row[DIMX];
        const float cv = row[2 * DIMX];
        const float dv = row[3 * DIMX];
        e = fmaxf(e, cv);
        const float o = bv * (av + a1 + cv + e) + a2 * dv
                        + av * fmaf(a3, e, dv) + cv * e;
        outp[(size_t)s * DIMX] = o;
    }

    if (chunk == NCHUNK - 1) {
        const size_t state_base = (size_t)BATCH * SEQ * DIMX;
        if (out_size >= (long long)(state_base + (size_t)BATCH * HD * HEADS)) {
            out[state_base + (size_t)b * HD * HEADS + (size_t)hd * HEADS + head] = e;
        }
    }
}

// ---------------------------------------------------------------------------
extern "C" void kernel_launch(void* const* d_in, const int* in_sizes, int n_in,
                              void* d_out, int out_size) {
    const float* x      = (const float*)d_in[0]; // [4, 2048, 2048]
    const float* W      = (const float*)d_in[1]; // [8192, 2048]
    const float* alphas = (const float*)d_in[2]; // [4]
    float* out = (float*)d_out;

    // tf32 rounding pass (both tensors)
    const size_t cvt_total = 2 * ((size_t)M_TOT * K_TOT / 4);
    cvt_kernel<<<(unsigned)((cvt_total + 255) / 256), 256>>>((const float4*)x, (const float4*)W);

    dim3 gemm_grid(N_TOT / BN, M_TOT / BM);      // (64, 64)
    gemm_tf32_kernel<<<gemm_grid, 256>>>();

    const int scan_threads = NCH * NCHUNK;       // 262144
    chunkmax_kernel<<<(scan_threads + 255) / 256, 256>>>();
    scan_out_kernel<<<(scan_threads + 255) / 256, 256>>>(alphas, out, (long long)out_size);
}